// round 2
// baseline (speedup 1.0000x reference)
#include <cuda_runtime.h>
#include <cooperative_groups.h>
#include <math.h>

namespace cg = cooperative_groups;

// Shapes fixed by setup_inputs: B=8, C=256, H=W=256, 4x4 grid of 64x64 blocks.
#define CC 256
#define HWF4 16384            // (H*W)/4 float4 per channel
#define NBLK 32768            // B*4*4*C block-channels
#define NGRP 128              // B*4*4 groups
#define BLK_N 4096.0f
#define N_INV (1.0f/4095.0f)
#define E_LAMBDA 1e-4f
#define TOTAL_ELEMS 134217728.0f

__device__ float2 g_sums[NBLK];    // (sum x, sum x^2) per block-channel
__device__ float2 g_muinv[NBLK];   // (mu, inv_denom)
__device__ float  g_s[NBLK];       // mean(eb) per block-channel

__device__ __forceinline__ float warpsum(float v) {
    #pragma unroll
    for (int o = 16; o; o >>= 1) v += __shfl_xor_sync(0xffffffffu, v, o);
    return v;
}

__device__ __forceinline__ float eb_elem(float a, float mu, float inv) {
    float d = a - mu;
    float y = d * d * inv + 0.5f;
    return a * (1.0f / (1.0f + __expf(-y)));
}

// ---------------- K1: per-block-channel sum / sumsq ----------
__global__ void k1_stats(const float4* __restrict__ x) {
    int idx = blockIdx.x;
    int c  = idx & 255;
    int t3 = idx >> 8;
    int j  = t3 & 3, i = (t3 >> 2) & 3, b = t3 >> 4;
    int base = (b * CC + c) * HWF4 + i * 4096 + j * 16;
    int t = threadIdx.x;               // 256 threads
    float s = 0.f, s2 = 0.f;
    #pragma unroll
    for (int it = 0; it < 4; it++) {
        int q  = it * 256 + t;
        float4 v = x[base + (q >> 4) * 64 + (q & 15)];
        s  += v.x + v.y + v.z + v.w;
        s2 += v.x * v.x + v.y * v.y + v.z * v.z + v.w * v.w;
    }
    __shared__ float sh[8], sh2[8];
    int w = t >> 5, lane = t & 31;
    s = warpsum(s); s2 = warpsum(s2);
    if (lane == 0) { sh[w] = s; sh2[w] = s2; }
    __syncthreads();
    if (t == 0) {
        float a = 0.f, b2 = 0.f;
        #pragma unroll
        for (int k = 0; k < 8; k++) { a += sh[k]; b2 += sh2[k]; }
        g_sums[idx] = make_float2(a, b2);
    }
}

// ---------------- K2: lambda + per-block (mu, inv) -----------
__global__ void k2_prep() {
    __shared__ float red[32];
    int t = threadIdx.x;               // 1024 threads
    float s = 0.f;
    for (int q = t; q < NBLK; q += 1024) s += g_sums[q].x;
    s = warpsum(s);
    if ((t & 31) == 0) red[t >> 5] = s;
    __syncthreads();
    if (t < 32) {
        float v = red[t];
        v = warpsum(v);
        if (t == 0) red[0] = v;
    }
    __syncthreads();
    float mean = red[0] / TOTAL_ELEMS;
    float lam  = E_LAMBDA * log1pf(fabsf(mean));
    for (int q = t; q < NBLK; q += 1024) {
        float2 ss = g_sums[q];
        float mu  = ss.x * (1.0f / BLK_N);
        float sd2 = ss.y - BLK_N * mu * mu;
        float inv = 1.0f / (4.0f * (sd2 * N_INV + lam));
        g_muinv[q] = make_float2(mu, inv);
    }
}

// ---------------- K3: fused eb-sum + SE + gated output -------
// Cluster of 8 CTAs = one (b,i,j) group (256 channels).
// CTA rank r owns channels [r*32, r*32+32); 1 warp per channel.
__global__ void __cluster_dims__(8, 1, 1) __launch_bounds__(1024, 1)
k3_fused(const float4* __restrict__ x,
         const float*  __restrict__ w1,
         const float*  __restrict__ w2,
         float4* __restrict__ out) {
    cg::cluster_group cluster = cg::this_cluster();
    int group = blockIdx.x >> 3;
    int rank  = blockIdx.x & 7;
    int w     = threadIdx.x >> 5;      // warp = local channel 0..31
    int lane  = threadIdx.x & 31;
    int c     = rank * 32 + w;
    int idx   = group * 256 + c;
    int b = group >> 4, i = (group >> 2) & 3, j = group & 3;
    int base  = (b * CC + c) * HWF4 + i * 4096 + j * 16;

    float2 mi = g_muinv[idx];
    float mu = mi.x, inv = mi.y;

    // ---- Phase A: per-channel sum(eb) (one warp per channel) ----
    float s = 0.f;
    #pragma unroll 8
    for (int k = 0; k < 32; k++) {
        int q = lane + k * 32;
        float4 v = x[base + (q >> 4) * 64 + (q & 15)];
        s += eb_elem(v.x, mu, inv) + eb_elem(v.y, mu, inv)
           + eb_elem(v.z, mu, inv) + eb_elem(v.w, mu, inv);
    }
    s = warpsum(s);
    if (lane == 0) g_s[idx] = s * (1.0f / BLK_N);
    __threadfence();
    cluster.sync();

    // ---- SE MLP (each CTA computes gates for its own 32 channels) ----
    __shared__ float s_s[256];
    __shared__ float s_h[16];
    __shared__ float s_g[32];
    if (threadIdx.x < 256) s_s[threadIdx.x] = g_s[group * 256 + threadIdx.x];
    __syncthreads();
    if (w < 16) {                      // warp w -> hidden unit w
        float acc = 0.f;
        #pragma unroll
        for (int k = 0; k < 8; k++) {
            int cidx = lane + k * 32;
            acc += w1[w * 256 + cidx] * s_s[cidx];
        }
        acc = warpsum(acc);
        if (lane == 0) s_h[w] = fmaxf(acc, 0.f);
    }
    __syncthreads();
    if (threadIdx.x < 32) {
        int cc = rank * 32 + threadIdx.x;
        float acc = 0.f;
        #pragma unroll
        for (int r = 0; r < 16; r++) acc += w2[cc * 16 + r] * s_h[r];
        s_g[threadIdx.x] = 1.0f / (1.0f + __expf(-acc));
    }
    __syncthreads();
    float gate = s_g[w];

    // ---- Phase B: re-read (L2-resident), gate, write out ----
    #pragma unroll 8
    for (int k = 0; k < 32; k++) {
        int q = lane + k * 32;
        int a = base + (q >> 4) * 64 + (q & 15);
        float4 v = x[a];
        float4 o;
        o.x = eb_elem(v.x, mu, inv) * gate;
        o.y = eb_elem(v.y, mu, inv) * gate;
        o.z = eb_elem(v.z, mu, inv) * gate;
        o.w = eb_elem(v.w, mu, inv) * gate;
        out[a] = o;
    }
}

extern "C" void kernel_launch(void* const* d_in, const int* in_sizes, int n_in,
                              void* d_out, int out_size) {
    const float4* x  = (const float4*)d_in[0];
    const float*  w1 = (const float*)d_in[1];
    const float*  w2 = (const float*)d_in[2];
    float4* out = (float4*)d_out;

    k1_stats<<<NBLK, 256>>>(x);
    k2_prep<<<1, 1024>>>();
    k3_fused<<<NGRP * 8, 1024>>>(x, w1, w2, out);
}

// round 3
// speedup vs baseline: 2.3004x; 2.3004x over previous
#include <cuda_runtime.h>
#include <math.h>

// Shapes fixed by setup_inputs: B=8, C=256, H=W=256, 4x4 grid of 64x64 blocks.
#define CC 256
#define HWF4 16384            // (H*W)/4 float4 per channel
#define NBLK 32768            // B*4*4*C block-channels
#define NGRP 128              // B*4*4 groups
#define BLK_N 4096.0f
#define N_INV (1.0f/4095.0f)
#define E_LAMBDA 1e-4f
#define TOTAL_ELEMS 134217728.0f

__device__ float2 g_sums[NBLK];    // (sum x, sum x^2) per block-channel
__device__ float2 g_muinv[NBLK];   // (mu, inv with exact lambda)
__device__ float  g_s[NBLK];       // mean(eb) per block-channel (lambda~0 approx)
__device__ float  g_gate[NBLK];    // SE gate
__device__ float  g_lambda;        // dynamic lambda

__device__ __forceinline__ float warpsum(float v) {
    #pragma unroll
    for (int o = 16; o; o >>= 1) v += __shfl_xor_sync(0xffffffffu, v, o);
    return v;
}

__device__ __forceinline__ float sigm(float y) {
    float e = __expf(-y);
    return __fdividef(1.0f, 1.0f + e);
}

__device__ __forceinline__ float eb_elem(float a, float mu, float inv) {
    float d = a - mu;
    return a * sigm(fmaf(d * d, inv, 0.5f));
}

// ---- K1: read x once; per-block stats AND eb-sum (registers resident) ----
__global__ void __launch_bounds__(256) k1_stats_ebsum(const float4* __restrict__ x) {
    int idx = blockIdx.x;
    int c  = idx & 255;
    int t3 = idx >> 8;
    int j  = t3 & 3, i = (t3 >> 2) & 3, b = t3 >> 4;
    int base = (b * CC + c) * HWF4 + i * 4096 + j * 16;
    int t = threadIdx.x;

    // Load 16 elements into registers, accumulate sum/sumsq
    float4 v[4];
    float s = 0.f, s2 = 0.f;
    #pragma unroll
    for (int it = 0; it < 4; it++) {
        int q = it * 256 + t;
        v[it] = x[base + (q >> 4) * 64 + (q & 15)];
        s  += v[it].x + v[it].y + v[it].z + v[it].w;
        s2 += v[it].x * v[it].x + v[it].y * v[it].y
            + v[it].z * v[it].z + v[it].w * v[it].w;
    }

    __shared__ float sh[8], sh2[8];
    __shared__ float s_mu, s_inv;
    int w = t >> 5, lane = t & 31;
    s = warpsum(s); s2 = warpsum(s2);
    if (lane == 0) { sh[w] = s; sh2[w] = s2; }
    __syncthreads();
    if (t == 0) {
        float a = 0.f, b2 = 0.f;
        #pragma unroll
        for (int k = 0; k < 8; k++) { a += sh[k]; b2 += sh2[k]; }
        g_sums[idx] = make_float2(a, b2);
        float mu  = a * (1.0f / BLK_N);
        float sd2 = b2 - BLK_N * mu * mu;
        s_mu  = mu;
        // lambda=0 approximation for the SE statistic only (error ~1e-9 rel;
        // exact lambda ~1e-8 vs variance ~1). 1e-12 floor kills sd2=0 NaN.
        s_inv = __fdividef(1.0f, 4.0f * (sd2 * N_INV + 1e-12f));
    }
    __syncthreads();
    float mu = s_mu, inv = s_inv;

    // eb-sum from registers (no re-read)
    float es = 0.f;
    #pragma unroll
    for (int it = 0; it < 4; it++) {
        es += eb_elem(v[it].x, mu, inv) + eb_elem(v[it].y, mu, inv)
            + eb_elem(v[it].z, mu, inv) + eb_elem(v[it].w, mu, inv);
    }
    es = warpsum(es);
    if (lane == 0) sh[w] = es;
    __syncthreads();
    if (t == 0) {
        float a = 0.f;
        #pragma unroll
        for (int k = 0; k < 8; k++) a += sh[k];
        g_s[idx] = a * (1.0f / BLK_N);
    }
}

// ---- K2a: global lambda (deterministic single-CTA reduction) ----
__global__ void k2a_lambda() {
    __shared__ float red[32];
    int t = threadIdx.x;               // 1024 threads
    float s = 0.f;
    for (int q = t; q < NBLK; q += 1024) s += g_sums[q].x;
    s = warpsum(s);
    if ((t & 31) == 0) red[t >> 5] = s;
    __syncthreads();
    if (t < 32) {
        float vv = warpsum(red[t]);
        if (t == 0) {
            float mean = vv / TOTAL_ELEMS;
            g_lambda = E_LAMBDA * log1pf(fabsf(mean));
        }
    }
}

// ---- K2b: per-block (mu, inv_exact) + SE MLP -> gates ----
__global__ void __launch_bounds__(256) k2b_se(const float* __restrict__ w1,
                                              const float* __restrict__ w2) {
    __shared__ float s_s[256];
    __shared__ float s_h[16];
    int g    = blockIdx.x;             // 0..127
    int t    = threadIdx.x;            // 256 threads: one channel each
    int idx  = g * 256 + t;
    float lam = g_lambda;

    float2 ss = g_sums[idx];
    float mu  = ss.x * (1.0f / BLK_N);
    float sd2 = ss.y - BLK_N * mu * mu;
    float inv = __fdividef(1.0f, 4.0f * (sd2 * N_INV + lam));
    g_muinv[idx] = make_float2(mu, inv);

    s_s[t] = g_s[idx];
    __syncthreads();
    int w = t >> 5, lane = t & 31;
    #pragma unroll
    for (int rr = 0; rr < 2; rr++) {
        int r = w * 2 + rr;            // 8 warps x 2 = 16 hidden units
        float acc = 0.f;
        #pragma unroll
        for (int k = 0; k < 8; k++) {
            int cidx = lane + k * 32;
            acc += w1[r * 256 + cidx] * s_s[cidx];
        }
        acc = warpsum(acc);
        if (lane == 0) s_h[r] = fmaxf(acc, 0.f);
    }
    __syncthreads();
    float acc = 0.f;
    #pragma unroll
    for (int r = 0; r < 16; r++) acc += w2[t * 16 + r] * s_h[r];
    g_gate[idx] = sigm(acc);
}

// ---- K3: out = eb(x; exact lambda) * gate ----
__global__ void __launch_bounds__(256) k3_out(const float4* __restrict__ x,
                                              float4* __restrict__ out) {
    int idx = blockIdx.x;
    int c  = idx & 255;
    int t3 = idx >> 8;
    int j  = t3 & 3, i = (t3 >> 2) & 3, b = t3 >> 4;
    int base = (b * CC + c) * HWF4 + i * 4096 + j * 16;
    float2 mi  = g_muinv[idx];
    float gate = g_gate[idx];
    int t = threadIdx.x;
    #pragma unroll
    for (int it = 0; it < 4; it++) {
        int q = it * 256 + t;
        int a = base + (q >> 4) * 64 + (q & 15);
        float4 vv = x[a];
        float4 o;
        o.x = eb_elem(vv.x, mi.x, mi.y) * gate;
        o.y = eb_elem(vv.y, mi.x, mi.y) * gate;
        o.z = eb_elem(vv.z, mi.x, mi.y) * gate;
        o.w = eb_elem(vv.w, mi.x, mi.y) * gate;
        out[a] = o;
    }
}

extern "C" void kernel_launch(void* const* d_in, const int* in_sizes, int n_in,
                              void* d_out, int out_size) {
    const float4* x  = (const float4*)d_in[0];
    const float*  w1 = (const float*)d_in[1];
    const float*  w2 = (const float*)d_in[2];
    float4* out = (float4*)d_out;

    k1_stats_ebsum<<<NBLK, 256>>>(x);
    k2a_lambda<<<1, 1024>>>();
    k2b_se<<<NGRP, 256>>>(w1, w2);
    k3_out<<<NBLK, 256>>>(x, out);
}